// round 11
// baseline (speedup 1.0000x reference)
#include <cuda_runtime.h>
#include <cuda_bf16.h>
#include <cuda_fp16.h>
#include <cstdint>
#include <cstddef>

// ---------------- problem constants ----------------
#define H_DIM   2048
#define V_DIM   32000
#define NROWS   2048            // B*T rows per model
#define BM      128
#define BN      256
#define BK      64              // fp16 elems per K chunk (128 bytes/row)
#define NTILES  125             // 32000 / 256
#define NITEMS  (NTILES * 32)   // 4000 items = (nt, model, mgroup)
#define KCH     32              // K-chunks per item (2048/64)
#define GRID    296             // 2 * 148 SMs (occ 2)
#define THREADS 256
#define PARTS   500             // partials per row = NTILES*4
#define L2E     1.4426950408889634f
#define LN2     0.6931471805599453f

// ---------------- SMEM ----------------
#define A_BYTES (BM * 128)              // 16384
#define B_BYTES (BN * 128)              // 32768
#define BUF_B   (A_BYTES + B_BYTES)     // 49152
#define SMEM_DATA 1024
#define SMEM_TOTAL (SMEM_DATA + 2 * BUF_B)   // 99328 -> 2 CTAs/SM

// ---------------- device scratch ----------------
__device__ __half g_Wh[2][(size_t)V_DIM * H_DIM];
__device__ __half g_xh[2][(size_t)NROWS * H_DIM];   // pre-scaled by log2(e)
__device__ float2   g_part[(size_t)2 * NROWS * 512];
__device__ float    g_logp[2 * NROWS];
__device__ float    g_maskf[2 * NROWS];
__device__ int      g_y64;
__device__ unsigned g_ticket;

// ---------------- helpers ----------------
__device__ __forceinline__ uint32_t smem_u32(const void* p) {
    uint32_t a;
    asm("{ .reg .u64 t; cvta.to.shared.u64 t, %1; cvt.u32.u64 %0, t; }"
        : "=r"(a) : "l"(p));
    return a;
}

#define SW128(o) ((o) ^ (((o) >> 3) & 0x70))

__device__ __forceinline__ void cp_async16(uint32_t saddr, const void* gaddr) {
    asm volatile("cp.async.cg.shared.global [%0], [%1], 16;"
                 :: "r"(saddr), "l"(gaddr) : "memory");
}

__device__ __forceinline__ void cp_async_mbar_arrive(uint32_t mbar) {
    asm volatile("cp.async.mbarrier.arrive.noinc.shared.b64 [%0];"
                 :: "r"(mbar) : "memory");
}

#define MBARRIER_INIT(addr, cnt) \
    asm volatile("mbarrier.init.shared.b64 [%0], %1;" \
        :: "r"((uint32_t)(addr)), "r"((uint32_t)(cnt)) : "memory")

#define MBARRIER_ARRIVE(addr) \
    asm volatile("mbarrier.arrive.shared.b64 _, [%0];" \
        :: "r"((uint32_t)(addr)) : "memory")

#define MBARRIER_WAIT_PARITY(addr, par) do {                                   \
    uint32_t _mb = (uint32_t)(addr); uint32_t _pp = (uint32_t)(par);           \
    uint32_t _done;                                                            \
    asm volatile("{\n\t.reg .pred p;\n\t"                                      \
        "mbarrier.try_wait.parity.acquire.cta.shared::cta.b64 p, [%1], %2;\n\t"\
        "selp.b32 %0, 1, 0, p;\n\t}"                                           \
        : "=r"(_done) : "r"(_mb), "r"(_pp) : "memory");                        \
    if (!_done) {                                                              \
        asm volatile("{\n\t.reg .pred P1;\n\t"                                 \
            "WAIT_LOOP_%=:\n\t"                                                \
            "mbarrier.try_wait.parity.acquire.cta.shared::cta.b64 P1, [%0], %1, 0x989680;\n\t" \
            "@P1 bra.uni WAIT_DONE_%=;\n\t"                                    \
            "bra.uni WAIT_LOOP_%=;\n\t"                                        \
            "WAIT_DONE_%=:\n\t}"                                               \
            :: "r"(_mb), "r"(_pp) : "memory");                                 \
    }                                                                          \
} while (0)

__device__ __forceinline__ void ldsm_x4(uint32_t (&r)[4], uint32_t addr) {
    asm volatile("ldmatrix.sync.aligned.m8n8.x4.shared.b16 {%0,%1,%2,%3}, [%4];"
        : "=r"(r[0]), "=r"(r[1]), "=r"(r[2]), "=r"(r[3]) : "r"(addr));
}

// fp16 MMA with f16 accumulators: D(16x8) += A(16x16) * B(16x8)
__device__ __forceinline__ void mma16816h(uint32_t (&d)[2], const uint32_t (&a)[4],
                                          uint32_t b0, uint32_t b1) {
    asm volatile(
        "mma.sync.aligned.m16n8k16.row.col.f16.f16.f16.f16 "
        "{%0,%1}, {%2,%3,%4,%5}, {%6,%7}, {%0,%1};"
        : "+r"(d[0]), "+r"(d[1])
        : "r"(a[0]), "r"(a[1]), "r"(a[2]), "r"(a[3]), "r"(b0), "r"(b1));
}

// ---------------- dummy (shifts ncu capture onto dpo_main_kernel) ------
__global__ void dummy_kernel() {}

// ---------------- merged fp32 -> fp16 conversion -----------------------
#define WN4 (V_DIM * H_DIM / 4)     // 16,384,000
#define XN4 (NROWS * H_DIM / 4)     // 1,048,576

__global__ void cvt_all_kernel(const float* __restrict__ x,
                               const float* __restrict__ rx,
                               const float* __restrict__ W,
                               const float* __restrict__ rW) {
    int i = blockIdx.x * blockDim.x + threadIdx.x;
    const float* src;
    __half* dst;
    float scale;
    int off;
    if (i < WN4)                { src = W;  dst = g_Wh[0]; scale = 1.0f; off = i; }
    else if (i < 2 * WN4)       { src = rW; dst = g_Wh[1]; scale = 1.0f; off = i - WN4; }
    else if (i < 2 * WN4 + XN4) { src = x;  dst = g_xh[0]; scale = L2E;  off = i - 2 * WN4; }
    else                        { src = rx; dst = g_xh[1]; scale = L2E;  off = i - 2 * WN4 - XN4; }
    float4 v = reinterpret_cast<const float4*>(src)[off];
    __half2 lo = __floats2half2_rn(v.x * scale, v.y * scale);
    __half2 hi = __floats2half2_rn(v.z * scale, v.w * scale);
    uint2 o;
    o.x = *reinterpret_cast<unsigned*>(&lo);
    o.y = *reinterpret_cast<unsigned*>(&hi);
    reinterpret_cast<uint2*>(dst)[off] = o;
}

// ---------------- y dtype detect + ticket reset ----------------
__global__ void detect_kernel(const int* __restrict__ y32) {
    if (threadIdx.x == 0) {
        int z = 0;
        for (int i = 0; i < 32; i++)
            if (y32[2 * i + 1] == 0) z++;
        g_y64 = (z >= 28) ? 1 : 0;
        g_ticket = 0;
    }
}

// ---------------- chunk loader: A (128x128B) + B (256x128B) fp16 ------
__device__ __forceinline__ void load_chunk(
    uint32_t dstbase,
    const __half* __restrict__ xr,
    const __half* __restrict__ wp,
    int kc, int tid)
{
    #pragma unroll
    for (int j = 0; j < 4; j++) {                 // A: 1024 x 16B segs
        int idx = j * THREADS + tid;
        int row = idx >> 3, seg = idx & 7;
        uint32_t sa = dstbase + SW128((uint32_t)(row * 128 + seg * 16));
        cp_async16(sa, xr + (size_t)row * H_DIM + kc * BK + seg * 8);
    }
    #pragma unroll
    for (int j = 0; j < 8; j++) {                 // B: 2048 x 16B segs
        int idx = j * THREADS + tid;
        int row = idx >> 3, seg = idx & 7;
        uint32_t sa = dstbase + A_BYTES + SW128((uint32_t)(row * 128 + seg * 16));
        cp_async16(sa, wp + (size_t)row * H_DIM + kc * BK + seg * 8);
    }
}

// decode item -> source pointers + partial slot base
struct ItemPtrs {
    const __half* xr;
    const __half* wp;
    size_t pbase;     // g_part base: ((model*16+mg)*128)*512 + nt*4
};
__device__ __forceinline__ ItemPtrs decode_item(unsigned it) {
    unsigned itc = (it < NITEMS) ? it : 0u;
    unsigned nt = itc >> 5;
    unsigned rem = itc & 31u;
    unsigned model = rem >> 4;
    unsigned mg = rem & 15u;
    ItemPtrs p;
    p.xr = g_xh[model] + (size_t)(mg * BM) * H_DIM;
    p.wp = g_Wh[model] + (size_t)(nt * BN) * H_DIM;
    p.pbase = ((size_t)((model * 16 + mg) * 128)) * 512 + nt * 4;
    return p;
}

// ---------------- main fused GEMM (f16 acc) + per-tile LSE ------------
__global__ void __launch_bounds__(THREADS, 2) dpo_main_kernel() {
    extern __shared__ char smem[];
    const uint32_t sb = smem_u32(smem);
    const int tid = threadIdx.x;
    const int lid = tid & 31;
    const int wid = tid >> 5;
    const int wm  = wid >> 2;       // 0..1 (M position, 64 rows each)
    const int wn  = wid & 3;        // 0..3 (N position, 64 cols each)

    const uint32_t mb_full0  = sb;          // full[b] at sb + b*8
    const uint32_t mb_empty0 = sb + 16;     // empty[b] at sb + 16 + b*8
    unsigned* sm_next = (unsigned*)(smem + 32);

    if (tid == 0) {
        #pragma unroll
        for (int b = 0; b < 2; b++) {
            MBARRIER_INIT(mb_full0  + b * 8, THREADS);
            MBARRIER_INIT(mb_empty0 + b * 8, THREADS);
        }
    }
    __syncthreads();

    // fetch two tickets
    unsigned it0, it1;
    if (tid == 0) *sm_next = atomicAdd(&g_ticket, 1u);
    __syncthreads();
    it0 = *sm_next;
    __syncthreads();
    if (tid == 0) *sm_next = atomicAdd(&g_ticket, 1u);
    __syncthreads();
    it1 = *sm_next;
    __syncthreads();

    if (it0 >= NITEMS) return;

    ItemPtrs cur = decode_item(it0);
    ItemPtrs nxt = decode_item(it1);

    // swizzled base offsets (relative to buffer base; 128B rows, SW128)
    const int a_row0 = wm * 64 + (lid & 15);
    const uint32_t a_kh = (uint32_t)((lid >> 4) * 16);
    const int b_row0 = wn * 64 + (lid & 7) + ((lid >> 4) << 3);
    const uint32_t b_kh = (uint32_t)(((lid >> 3) & 1) * 16);

    uint32_t a_off[4], b_off[4];
    #pragma unroll
    for (int i = 0; i < 4; i++)
        a_off[i] = SW128((uint32_t)((a_row0 + i * 16) * 128) + a_kh);
    #pragma unroll
    for (int j = 0; j < 4; j++)
        b_off[j] = SW128((uint32_t)((b_row0 + j * 16) * 128) + b_kh) + A_BYTES;

    uint32_t acc[4][8][2];   // f16x2 accumulators, warp tile 64x64
    #pragma unroll
    for (int i = 0; i < 4; i++)
        #pragma unroll
        for (int j = 0; j < 8; j++)
            { acc[i][j][0] = 0u; acc[i][j][1] = 0u; }

    // prologue: chunk 0 into buffer 0
    load_chunk(sb + SMEM_DATA + 0 * BUF_B, cur.xr, cur.wp, 0, tid);
    cp_async_mbar_arrive(mb_full0 + 0 * 8);

    int cc = 0;   // flat chunk counter across items
    #pragma unroll 1
    while (it0 < NITEMS) {
        #pragma unroll 1
        for (int j = 0; j < KCH; j++, cc++) {
            const int b = cc & 1;

            // producer FIRST (2-stage, distance 1): chunk cc+1 -> buffer b^1
            const int jn = j + 1;
            const bool nxtgrp = (jn >= KCH);
            if (!nxtgrp || it1 < NITEMS) {
                const ItemPtrs& src = nxtgrp ? nxt : cur;
                const int b2 = b ^ 1;
                if (cc >= 1)
                    MBARRIER_WAIT_PARITY(mb_empty0 + b2 * 8, ((cc - 1) >> 1) & 1);
                load_chunk(sb + SMEM_DATA + b2 * BUF_B, src.xr, src.wp,
                           jn & (KCH - 1), tid);
                cp_async_mbar_arrive(mb_full0 + b2 * 8);
            }

            // consumer: chunk cc
            MBARRIER_WAIT_PARITY(mb_full0 + b * 8, (cc >> 1) & 1);

            const uint32_t bufbase = sb + SMEM_DATA + b * BUF_B;
            #pragma unroll
            for (int ks = 0; ks < 4; ks++) {
                const uint32_t kx = (uint32_t)(ks << 5);
                uint32_t a_frag[4][4], b_frag[4][4];
                #pragma unroll
                for (int i = 0; i < 4; i++)
                    ldsm_x4(a_frag[i], (bufbase + a_off[i]) ^ kx);
                #pragma unroll
                for (int j2 = 0; j2 < 4; j2++)
                    ldsm_x4(b_frag[j2], (bufbase + b_off[j2]) ^ kx);
                #pragma unroll
                for (int j2 = 0; j2 < 4; j2++)
                    #pragma unroll
                    for (int i = 0; i < 4; i++) {
                        mma16816h(acc[i][j2 * 2],     a_frag[i], b_frag[j2][0], b_frag[j2][1]);
                        mma16816h(acc[i][j2 * 2 + 1], a_frag[i], b_frag[j2][2], b_frag[j2][3]);
                    }
            }
            MBARRIER_ARRIVE(mb_empty0 + b * 8);
        }

        // epilogue: per-tile max / sum-exp2 over this warp's 64 cols
        #pragma unroll
        for (int i = 0; i < 4; i++) {
            #pragma unroll
            for (int rh = 0; rh < 2; rh++) {
                __half2 m2 = __floats2half2_rn(-60000.f, -60000.f);
                #pragma unroll
                for (int j = 0; j < 8; j++) {
                    __half2 v = *reinterpret_cast<__half2*>(&acc[i][j][rh]);
                    m2 = __hmax2(m2, v);
                }
                float2 mf = __half22float2(m2);
                float rmax = fmaxf(mf.x, mf.y);
                rmax = fmaxf(rmax, __shfl_xor_sync(0xffffffffu, rmax, 1));
                rmax = fmaxf(rmax, __shfl_xor_sync(0xffffffffu, rmax, 2));
                __half2 rm2 = __float2half2_rn(rmax);
                __half2 s2 = __float2half2_rn(0.f);
                #pragma unroll
                for (int j = 0; j < 8; j++) {
                    __half2 v = *reinterpret_cast<__half2*>(&acc[i][j][rh]);
                    s2 = __hadd2(s2, h2exp2(__hsub2(v, rm2)));
                }
                float2 sf = __half22float2(s2);
                float st = sf.x + sf.y;
                st += __shfl_xor_sync(0xffffffffu, st, 1);
                st += __shfl_xor_sync(0xffffffffu, st, 2);
                if ((lid & 3) == 0) {
                    int row = wm * 64 + i * 16 + rh * 8 + (lid >> 2);
                    g_part[cur.pbase + (size_t)row * 512 + wn] =
                        make_float2(rmax, st);
                }
            }
        }
        #pragma unroll
        for (int i = 0; i < 4; i++)
            #pragma unroll
            for (int j = 0; j < 8; j++)
                { acc[i][j][0] = 0u; acc[i][j][1] = 0u; }

        // rotate items; fetch new lookahead ticket
        it0 = it1;
        cur = nxt;
        __syncthreads();
        if (tid == 0)
            *sm_next = (it0 < NITEMS) ? atomicAdd(&g_ticket, 1u) : NITEMS;
        __syncthreads();
        it1 = *sm_next;
        nxt = decode_item(it1);
    }
}

// ---------------- combine 500 partials/row + exact fp32 token dot -----
__global__ void reduce_kernel(const void* __restrict__ yp,
                              const float* __restrict__ x,
                              const float* __restrict__ rx,
                              const float* __restrict__ W,
                              const float* __restrict__ rW) {
    int wid = threadIdx.x >> 5, lid = threadIdx.x & 31;
    int row_all = blockIdx.x * 8 + wid;        // 512 blocks -> 4096 rows
    if (row_all >= 2 * NROWS) return;
    int model = row_all >> 11;
    int r     = row_all & (NROWS - 1);
    int mg    = r >> 7;
    int localrow = r & 127;

    long long yv = g_y64 ? ((const long long*)yp)[r]
                         : (long long)((const int*)yp)[r];
    bool mask = (yv != -100);
    int safe = mask ? (int)yv : 0;

    // exact token logit from ORIGINAL fp32 inputs (natural units)
    const float4* xr = (const float4*)((model ? rx : x) + (size_t)r * H_DIM);
    const float4* wr = (const float4*)((model ? rW : W) + (size_t)safe * H_DIM);
    float acc = 0.f;
    #pragma unroll 4
    for (int t = 0; t < 16; t++) {
        int i = t * 32 + lid;
        float4 a = xr[i];
        float4 b = wr[i];
        acc = fmaf(a.x, b.x, acc);
        acc = fmaf(a.y, b.y, acc);
        acc = fmaf(a.z, b.z, acc);
        acc = fmaf(a.w, b.w, acc);
    }
    #pragma unroll
    for (int off = 16; off; off >>= 1)
        acc += __shfl_xor_sync(0xffffffffu, acc, off);

    // combine PARTS = 500 (m, s) partials for this row
    const float2* pp = &g_part[((size_t)((model * 16 + mg) * 128 + localrow)) * 512];
    float M = -3.0e38f, S = 0.f;
    for (int t = 0; t < 16; t++) {
        int idx = t * 32 + lid;
        if (idx < PARTS) {
            float2 v = pp[idx];
            float mnew = fmaxf(M, v.x);
            S = S * exp2f(M - mnew) + v.y * exp2f(v.x - mnew);
            M = mnew;
        }
    }
    #pragma unroll
    for (int off = 16; off; off >>= 1) {
        float Mo = __shfl_xor_sync(0xffffffffu, M, off);
        float So = __shfl_xor_sync(0xffffffffu, S, off);
        float mnew = fmaxf(M, Mo);
        S = S * exp2f(M - mnew) + So * exp2f(Mo - mnew);
        M = mnew;
    }
    float lse_nat = LN2 * (M + log2f(S));
    if (lid == 0) {
        g_logp[row_all]  = mask ? (acc - lse_nat) : 0.f;
        g_maskf[row_all] = mask ? 1.f : 0.f;
    }
}

// ---------------- final loss ----------------
__global__ void final_kernel(float* __restrict__ out) {
    __shared__ float avg[8];
    int wid = threadIdx.x >> 5, lid = threadIdx.x & 31;
    float sl = 0.f, sm = 0.f;
    for (int i = lid; i < 512; i += 32) {
        sl += g_logp[wid * 512 + i];
        sm += g_maskf[wid * 512 + i];
    }
    #pragma unroll
    for (int off = 16; off; off >>= 1) {
        sl += __shfl_xor_sync(0xffffffffu, sl, off);
        sm += __shfl_xor_sync(0xffffffffu, sm, off);
    }
    if (lid == 0) avg[wid] = (sm > 0.f) ? (sl / sm) : 0.f;
    __syncthreads();
    if (threadIdx.x == 0) {
        const float BETA = 0.1f;
        float loss = 0.f;
        for (int b = 0; b < 4; b++) {
            float lr = avg[b] - avg[4 + b];
            float z = (b < 2) ? (BETA * lr) : (-BETA * lr);
            float sig = 1.f / (1.f + expf(-z));
            loss += 1.f - sig;
        }
        out[0] = loss / 2.f;
    }
}

// ---------------- launcher ----------------
extern "C" void kernel_launch(void* const* d_in, const int* in_sizes, int n_in,
                              void* d_out, int out_size) {
    const float* x  = (const float*)d_in[0];
    const float* rx = (const float*)d_in[1];
    const void*  y  = d_in[2];
    const float* W  = (const float*)d_in[3];
    const float* rW = (const float*)d_in[4];
    float* out = (float*)d_out;

    cudaFuncSetAttribute(dpo_main_kernel,
                         cudaFuncAttributeMaxDynamicSharedMemorySize, SMEM_TOTAL);

    // 3 dummies shift dpo_main_kernel to launch #6 -> ncu -s 5 -c 1 captures it
    dummy_kernel<<<1, 32>>>();
    dummy_kernel<<<1, 32>>>();
    dummy_kernel<<<1, 32>>>();

    const int cvt_blocks = (2 * WN4 + 2 * XN4) / 256;   // exact
    cvt_all_kernel<<<cvt_blocks, 256>>>(x, rx, W, rW);
    detect_kernel<<<1, 32>>>((const int*)y);
    dpo_main_kernel<<<GRID, THREADS, SMEM_TOTAL>>>();
    reduce_kernel<<<512, 256>>>(y, x, rx, W, rW);
    final_kernel<<<1, 256>>>(out);
}

// round 12
// speedup vs baseline: 1.0370x; 1.0370x over previous
#include <cuda_runtime.h>
#include <cuda_bf16.h>
#include <cuda_fp16.h>
#include <cstdint>
#include <cstddef>

// ---------------- problem constants ----------------
#define H_DIM   2048
#define V_DIM   32000
#define NROWS   2048            // B*T rows per model
#define BM      256             // 2 mgroups of 128 per item
#define BN      256
#define BK      64              // fp16 elems per K chunk (128 bytes/row)
#define NTILES  125             // 32000 / 256
#define NITEMS  (NTILES * 16)   // 2000 items = (nt, model, mgpair)
#define KCH     32              // K-chunks per item (2048/64)
#define GRID    148             // occ 1, all SMs
#define THREADS 256
#define PARTS   500             // partials per row = NTILES*4
#define L2E     1.4426950408889634f
#define LN2     0.6931471805599453f

// ---------------- SMEM ----------------
#define A_BYTES (BM * 128)              // 32768
#define B_BYTES (BN * 128)              // 32768
#define BUF_B   (A_BYTES + B_BYTES)     // 65536
#define SMEM_DATA 1024
#define SMEM_TOTAL (SMEM_DATA + 2 * BUF_B)   // 132096 -> 1 CTA/SM

// ---------------- device scratch ----------------
__device__ __half g_Wh[2][(size_t)V_DIM * H_DIM];
__device__ __half g_xh[2][(size_t)NROWS * H_DIM];   // pre-scaled by log2(e)
__device__ float2   g_part[(size_t)2 * NROWS * 512];
__device__ float    g_logp[2 * NROWS];
__device__ float    g_maskf[2 * NROWS];
__device__ int      g_y64;
__device__ unsigned g_ticket;

// ---------------- helpers ----------------
__device__ __forceinline__ uint32_t smem_u32(const void* p) {
    uint32_t a;
    asm("{ .reg .u64 t; cvta.to.shared.u64 t, %1; cvt.u32.u64 %0, t; }"
        : "=r"(a) : "l"(p));
    return a;
}

#define SW128(o) ((o) ^ (((o) >> 3) & 0x70))

__device__ __forceinline__ void cp_async16(uint32_t saddr, const void* gaddr) {
    asm volatile("cp.async.cg.shared.global [%0], [%1], 16;"
                 :: "r"(saddr), "l"(gaddr) : "memory");
}

__device__ __forceinline__ void cp_async_mbar_arrive(uint32_t mbar) {
    asm volatile("cp.async.mbarrier.arrive.noinc.shared.b64 [%0];"
                 :: "r"(mbar) : "memory");
}

#define MBARRIER_INIT(addr, cnt) \
    asm volatile("mbarrier.init.shared.b64 [%0], %1;" \
        :: "r"((uint32_t)(addr)), "r"((uint32_t)(cnt)) : "memory")

#define MBARRIER_ARRIVE(addr) \
    asm volatile("mbarrier.arrive.shared.b64 _, [%0];" \
        :: "r"((uint32_t)(addr)) : "memory")

#define MBARRIER_WAIT_PARITY(addr, par) do {                                   \
    uint32_t _mb = (uint32_t)(addr); uint32_t _pp = (uint32_t)(par);           \
    uint32_t _done;                                                            \
    asm volatile("{\n\t.reg .pred p;\n\t"                                      \
        "mbarrier.try_wait.parity.acquire.cta.shared::cta.b64 p, [%1], %2;\n\t"\
        "selp.b32 %0, 1, 0, p;\n\t}"                                           \
        : "=r"(_done) : "r"(_mb), "r"(_pp) : "memory");                        \
    if (!_done) {                                                              \
        asm volatile("{\n\t.reg .pred P1;\n\t"                                 \
            "WAIT_LOOP_%=:\n\t"                                                \
            "mbarrier.try_wait.parity.acquire.cta.shared::cta.b64 P1, [%0], %1, 0x989680;\n\t" \
            "@P1 bra.uni WAIT_DONE_%=;\n\t"                                    \
            "bra.uni WAIT_LOOP_%=;\n\t"                                        \
            "WAIT_DONE_%=:\n\t}"                                               \
            :: "r"(_mb), "r"(_pp) : "memory");                                 \
    }                                                                          \
} while (0)

__device__ __forceinline__ void ldsm_x4(uint32_t (&r)[4], uint32_t addr) {
    asm volatile("ldmatrix.sync.aligned.m8n8.x4.shared.b16 {%0,%1,%2,%3}, [%4];"
        : "=r"(r[0]), "=r"(r[1]), "=r"(r[2]), "=r"(r[3]) : "r"(addr));
}

// fp16 MMA with f16 accumulators: D(16x8) += A(16x16) * B(16x8)
__device__ __forceinline__ void mma16816h(uint32_t (&d)[2], const uint32_t (&a)[4],
                                          uint32_t b0, uint32_t b1) {
    asm volatile(
        "mma.sync.aligned.m16n8k16.row.col.f16.f16.f16.f16 "
        "{%0,%1}, {%2,%3,%4,%5}, {%6,%7}, {%0,%1};"
        : "+r"(d[0]), "+r"(d[1])
        : "r"(a[0]), "r"(a[1]), "r"(a[2]), "r"(a[3]), "r"(b0), "r"(b1));
}

// ---------------- merged fp32 -> fp16 conversion -----------------------
#define WN4 (V_DIM * H_DIM / 4)     // 16,384,000
#define XN4 (NROWS * H_DIM / 4)     // 1,048,576

__global__ void cvt_all_kernel(const float* __restrict__ x,
                               const float* __restrict__ rx,
                               const float* __restrict__ W,
                               const float* __restrict__ rW) {
    int i = blockIdx.x * blockDim.x + threadIdx.x;
    const float* src;
    __half* dst;
    float scale;
    int off;
    if (i < WN4)                { src = W;  dst = g_Wh[0]; scale = 1.0f; off = i; }
    else if (i < 2 * WN4)       { src = rW; dst = g_Wh[1]; scale = 1.0f; off = i - WN4; }
    else if (i < 2 * WN4 + XN4) { src = x;  dst = g_xh[0]; scale = L2E;  off = i - 2 * WN4; }
    else                        { src = rx; dst = g_xh[1]; scale = L2E;  off = i - 2 * WN4 - XN4; }
    float4 v = reinterpret_cast<const float4*>(src)[off];
    __half2 lo = __floats2half2_rn(v.x * scale, v.y * scale);
    __half2 hi = __floats2half2_rn(v.z * scale, v.w * scale);
    uint2 o;
    o.x = *reinterpret_cast<unsigned*>(&lo);
    o.y = *reinterpret_cast<unsigned*>(&hi);
    reinterpret_cast<uint2*>(dst)[off] = o;
}

// ---------------- y dtype detect + ticket reset ----------------
__global__ void detect_kernel(const int* __restrict__ y32) {
    if (threadIdx.x == 0) {
        int z = 0;
        for (int i = 0; i < 32; i++)
            if (y32[2 * i + 1] == 0) z++;
        g_y64 = (z >= 28) ? 1 : 0;
        g_ticket = 0;
    }
}

// ---------------- chunk loader: A (256x128B) + B (256x128B) fp16 ------
__device__ __forceinline__ void load_chunk(
    uint32_t dstbase,
    const __half* __restrict__ xr,
    const __half* __restrict__ wp,
    int kc, int tid)
{
    #pragma unroll
    for (int j = 0; j < 8; j++) {                 // A: 2048 x 16B segs
        int idx = j * THREADS + tid;
        int row = idx >> 3, seg = idx & 7;
        uint32_t sa = dstbase + SW128((uint32_t)(row * 128 + seg * 16));
        cp_async16(sa, xr + (size_t)row * H_DIM + kc * BK + seg * 8);
    }
    #pragma unroll
    for (int j = 0; j < 8; j++) {                 // B: 2048 x 16B segs
        int idx = j * THREADS + tid;
        int row = idx >> 3, seg = idx & 7;
        uint32_t sa = dstbase + A_BYTES + SW128((uint32_t)(row * 128 + seg * 16));
        cp_async16(sa, wp + (size_t)row * H_DIM + kc * BK + seg * 8);
    }
}

// decode item -> source pointers + partial slot base
struct ItemPtrs {
    const __half* xr;
    const __half* wp;
    size_t pbase;   // g_part base: (model*NROWS + mgp*256)*512 + nt*4
};
__device__ __forceinline__ ItemPtrs decode_item(unsigned it) {
    unsigned itc = (it < NITEMS) ? it : 0u;
    unsigned nt = itc >> 4;
    unsigned rem = itc & 15u;
    unsigned model = rem >> 3;
    unsigned mgp = rem & 7u;
    ItemPtrs p;
    p.xr = g_xh[model] + (size_t)(mgp * BM) * H_DIM;
    p.wp = g_Wh[model] + (size_t)(nt * BN) * H_DIM;
    p.pbase = ((size_t)(model * NROWS + mgp * BM)) * 512 + nt * 4;
    return p;
}

// ---------------- main fused GEMM (f16 acc, 256x256 block) ------------
__global__ void __launch_bounds__(THREADS, 1) dpo_main_kernel() {
    extern __shared__ char smem[];
    const uint32_t sb = smem_u32(smem);
    const int tid = threadIdx.x;
    const int lid = tid & 31;
    const int wid = tid >> 5;
    const int wm  = wid >> 2;       // 0..1 (M position, 128 rows each)
    const int wn  = wid & 3;        // 0..3 (N position, 64 cols each)

    const uint32_t mb_full0  = sb;          // full[b] at sb + b*8
    const uint32_t mb_empty0 = sb + 16;     // empty[b] at sb + 16 + b*8
    unsigned* sm_next = (unsigned*)(smem + 32);

    if (tid == 0) {
        #pragma unroll
        for (int b = 0; b < 2; b++) {
            MBARRIER_INIT(mb_full0  + b * 8, THREADS);
            MBARRIER_INIT(mb_empty0 + b * 8, THREADS);
        }
    }
    __syncthreads();

    // fetch two tickets
    unsigned it0, it1;
    if (tid == 0) *sm_next = atomicAdd(&g_ticket, 1u);
    __syncthreads();
    it0 = *sm_next;
    __syncthreads();
    if (tid == 0) *sm_next = atomicAdd(&g_ticket, 1u);
    __syncthreads();
    it1 = *sm_next;
    __syncthreads();

    if (it0 >= NITEMS) return;

    ItemPtrs cur = decode_item(it0);
    ItemPtrs nxt = decode_item(it1);

    // swizzled base offsets (relative to buffer base; 128B rows, SW128)
    // warp tile: 128 rows (wm*128), split as 2 halves (mgh) of 64 rows
    const int a_rowbase = wm * 128 + (lid & 15);
    const uint32_t a_kh = (uint32_t)((lid >> 4) * 16);
    const int b_row0 = wn * 64 + (lid & 7) + ((lid >> 4) << 3);
    const uint32_t b_kh = (uint32_t)(((lid >> 3) & 1) * 16);

    uint32_t a_off[2][4], b_off[4];
    #pragma unroll
    for (int h = 0; h < 2; h++)
        #pragma unroll
        for (int i = 0; i < 4; i++)
            a_off[h][i] = SW128((uint32_t)((a_rowbase + h * 64 + i * 16) * 128) + a_kh);
    #pragma unroll
    for (int j = 0; j < 4; j++)
        b_off[j] = SW128((uint32_t)((b_row0 + j * 16) * 128) + b_kh) + A_BYTES;

    uint32_t acc[2][4][8][2];   // [mgh][i][j][reg] f16x2, warp tile 128x64
    #pragma unroll
    for (int h = 0; h < 2; h++)
        #pragma unroll
        for (int i = 0; i < 4; i++)
            #pragma unroll
            for (int j = 0; j < 8; j++)
                { acc[h][i][j][0] = 0u; acc[h][i][j][1] = 0u; }

    // prologue: chunk 0 into buffer 0
    load_chunk(sb + SMEM_DATA + 0 * BUF_B, cur.xr, cur.wp, 0, tid);
    cp_async_mbar_arrive(mb_full0 + 0 * 8);

    int cc = 0;   // flat chunk counter across items
    #pragma unroll 1
    while (it0 < NITEMS) {
        #pragma unroll 1
        for (int j = 0; j < KCH; j++, cc++) {
            const int b = cc & 1;

            // producer FIRST (2-stage, distance 1): chunk cc+1 -> buffer b^1
            const int jn = j + 1;
            const bool nxtgrp = (jn >= KCH);
            if (!nxtgrp || it1 < NITEMS) {
                const ItemPtrs& src = nxtgrp ? nxt : cur;
                const int b2 = b ^ 1;
                if (cc >= 1)
                    MBARRIER_WAIT_PARITY(mb_empty0 + b2 * 8, ((cc - 1) >> 1) & 1);
                load_chunk(sb + SMEM_DATA + b2 * BUF_B, src.xr, src.wp,
                           jn & (KCH - 1), tid);
                cp_async_mbar_arrive(mb_full0 + b2 * 8);
            }

            // consumer: chunk cc
            MBARRIER_WAIT_PARITY(mb_full0 + b * 8, (cc >> 1) & 1);

            const uint32_t bufbase = sb + SMEM_DATA + b * BUF_B;
            #pragma unroll
            for (int ks = 0; ks < 4; ks++) {
                const uint32_t kx = (uint32_t)(ks << 5);
                uint32_t b_frag[4][4];
                #pragma unroll
                for (int j2 = 0; j2 < 4; j2++)
                    ldsm_x4(b_frag[j2], (bufbase + b_off[j2]) ^ kx);
                #pragma unroll
                for (int h = 0; h < 2; h++) {
                    uint32_t a_frag[4][4];
                    #pragma unroll
                    for (int i = 0; i < 4; i++)
                        ldsm_x4(a_frag[i], (bufbase + a_off[h][i]) ^ kx);
                    #pragma unroll
                    for (int j2 = 0; j2 < 4; j2++)
                        #pragma unroll
                        for (int i = 0; i < 4; i++) {
                            mma16816h(acc[h][i][j2 * 2],     a_frag[i],
                                      b_frag[j2][0], b_frag[j2][1]);
                            mma16816h(acc[h][i][j2 * 2 + 1], a_frag[i],
                                      b_frag[j2][2], b_frag[j2][3]);
                        }
                }
            }
            MBARRIER_ARRIVE(mb_empty0 + b * 8);
        }

        // epilogue: per-tile max / sum-exp2 over this warp's 64 cols x 128 rows
        #pragma unroll
        for (int h = 0; h < 2; h++) {
            #pragma unroll
            for (int i = 0; i < 4; i++) {
                #pragma unroll
                for (int rh = 0; rh < 2; rh++) {
                    __half2 m2 = __floats2half2_rn(-60000.f, -60000.f);
                    #pragma unroll
                    for (int j = 0; j < 8; j++) {
                        __half2 v = *reinterpret_cast<__half2*>(&acc[h][i][j][rh]);
                        m2 = __hmax2(m2, v);
                    }
                    float2 mf = __half22float2(m2);
                    float rmax = fmaxf(mf.x, mf.y);
                    rmax = fmaxf(rmax, __shfl_xor_sync(0xffffffffu, rmax, 1));
                    rmax = fmaxf(rmax, __shfl_xor_sync(0xffffffffu, rmax, 2));
                    __half2 rm2 = __float2half2_rn(rmax);
                    __half2 s2 = __float2half2_rn(0.f);
                    #pragma unroll
                    for (int j = 0; j < 8; j++) {
                        __half2 v = *reinterpret_cast<__half2*>(&acc[h][i][j][rh]);
                        s2 = __hadd2(s2, h2exp2(__hsub2(v, rm2)));
                    }
                    float2 sf = __half22float2(s2);
                    float st = sf.x + sf.y;
                    st += __shfl_xor_sync(0xffffffffu, st, 1);
                    st += __shfl_xor_sync(0xffffffffu, st, 2);
                    if ((lid & 3) == 0) {
                        int row = wm * 128 + h * 64 + i * 16 + rh * 8 + (lid >> 2);
                        g_part[cur.pbase + (size_t)row * 512 + wn] =
                            make_float2(rmax, st);
                    }
                }
            }
        }
        #pragma unroll
        for (int h = 0; h < 2; h++)
            #pragma unroll
            for (int i = 0; i < 4; i++)
                #pragma unroll
                for (int j = 0; j < 8; j++)
                    { acc[h][i][j][0] = 0u; acc[h][i][j][1] = 0u; }

        // rotate items; fetch new lookahead ticket
        it0 = it1;
        cur = nxt;
        __syncthreads();
        if (tid == 0)
            *sm_next = (it0 < NITEMS) ? atomicAdd(&g_ticket, 1u) : NITEMS;
        __syncthreads();
        it1 = *sm_next;
        nxt = decode_item(it1);
    }
}

// ---------------- combine 500 partials/row + exact fp32 token dot -----
__global__ void reduce_kernel(const void* __restrict__ yp,
                              const float* __restrict__ x,
                              const float* __restrict__ rx,
                              const float* __restrict__ W,
                              const float* __restrict__ rW) {
    int wid = threadIdx.x >> 5, lid = threadIdx.x & 31;
    int row_all = blockIdx.x * 8 + wid;        // 512 blocks -> 4096 rows
    if (row_all >= 2 * NROWS) return;
    int model = row_all >> 11;
    int r     = row_all & (NROWS - 1);

    long long yv = g_y64 ? ((const long long*)yp)[r]
                         : (long long)((const int*)yp)[r];
    bool mask = (yv != -100);
    int safe = mask ? (int)yv : 0;

    // exact token logit from ORIGINAL fp32 inputs (natural units)
    const float4* xr = (const float4*)((model ? rx : x) + (size_t)r * H_DIM);
    const float4* wr = (const float4*)((model ? rW : W) + (size_t)safe * H_DIM);
    float acc = 0.f;
    #pragma unroll 4
    for (int t = 0; t < 16; t++) {
        int i = t * 32 + lid;
        float4 a = xr[i];
        float4 b = wr[i];
        acc = fmaf(a.x, b.x, acc);
        acc = fmaf(a.y, b.y, acc);
        acc = fmaf(a.z, b.z, acc);
        acc = fmaf(a.w, b.w, acc);
    }
    #pragma unroll
    for (int off = 16; off; off >>= 1)
        acc += __shfl_xor_sync(0xffffffffu, acc, off);

    // combine PARTS = 500 (m, s) partials for this row
    const float2* pp = &g_part[((size_t)(model * NROWS + r)) * 512];
    float M = -3.0e38f, S = 0.f;
    for (int t = 0; t < 16; t++) {
        int idx = t * 32 + lid;
        if (idx < PARTS) {
            float2 v = pp[idx];
            float mnew = fmaxf(M, v.x);
            S = S * exp2f(M - mnew) + v.y * exp2f(v.x - mnew);
            M = mnew;
        }
    }
    #pragma unroll
    for (int off = 16; off; off >>= 1) {
        float Mo = __shfl_xor_sync(0xffffffffu, M, off);
        float So = __shfl_xor_sync(0xffffffffu, S, off);
        float mnew = fmaxf(M, Mo);
        S = S * exp2f(M - mnew) + So * exp2f(Mo - mnew);
        M = mnew;
    }
    float lse_nat = LN2 * (M + log2f(S));
    if (lid == 0) {
        g_logp[row_all]  = mask ? (acc - lse_nat) : 0.f;
        g_maskf[row_all] = mask ? 1.f : 0.f;
    }
}

// ---------------- final loss ----------------
__global__ void final_kernel(float* __restrict__ out) {
    __shared__ float avg[8];
    int wid = threadIdx.x >> 5, lid = threadIdx.x & 31;
    float sl = 0.f, sm = 0.f;
    for (int i = lid; i < 512; i += 32) {
        sl += g_logp[wid * 512 + i];
        sm += g_maskf[wid * 512 + i];
    }
    #pragma unroll
    for (int off = 16; off; off >>= 1) {
        sl += __shfl_xor_sync(0xffffffffu, sl, off);
        sm += __shfl_xor_sync(0xffffffffu, sm, off);
    }
    if (lid == 0) avg[wid] = (sm > 0.f) ? (sl / sm) : 0.f;
    __syncthreads();
    if (threadIdx.x == 0) {
        const float BETA = 0.1f;
        float loss = 0.f;
        for (int b = 0; b < 4; b++) {
            float lr = avg[b] - avg[4 + b];
            float z = (b < 2) ? (BETA * lr) : (-BETA * lr);
            float sig = 1.f / (1.f + expf(-z));
            loss += 1.f - sig;
        }
        out[0] = loss / 2.f;
    }
}

// ---------------- launcher ----------------
extern "C" void kernel_launch(void* const* d_in, const int* in_sizes, int n_in,
                              void* d_out, int out_size) {
    const float* x  = (const float*)d_in[0];
    const float* rx = (const float*)d_in[1];
    const void*  y  = d_in[2];
    const float* W  = (const float*)d_in[3];
    const float* rW = (const float*)d_in[4];
    float* out = (float*)d_out;

    cudaFuncSetAttribute(dpo_main_kernel,
                         cudaFuncAttributeMaxDynamicSharedMemorySize, SMEM_TOTAL);

    const int cvt_blocks = (2 * WN4 + 2 * XN4) / 256;   // exact
    cvt_all_kernel<<<cvt_blocks, 256>>>(x, rx, W, rW);
    detect_kernel<<<1, 32>>>((const int*)y);
    dpo_main_kernel<<<GRID, THREADS, SMEM_TOTAL>>>();
    reduce_kernel<<<512, 256>>>(y, x, rx, W, rW);
    final_kernel<<<1, 256>>>(out);
}

// round 13
// speedup vs baseline: 1.0490x; 1.0116x over previous
#include <cuda_runtime.h>
#include <cuda_bf16.h>
#include <cuda_fp16.h>
#include <cstdint>
#include <cstddef>

// ---------------- problem constants ----------------
#define H_DIM   2048
#define V_DIM   32000
#define NROWS   2048            // B*T rows per model
#define BM      256             // 2 mgroups of 128 per item
#define BN      256
#define BK      64              // fp16 elems per K chunk (128 bytes/row)
#define NTILES  125             // 32000 / 256
#define NITEMS  (NTILES * 16)   // 2000 items = (nt, model, mgpair)
#define KCH     32              // K-chunks per item (2048/64)
#define GRID    148             // occ 1, all SMs
#define THREADS 256
#define PARTS   500             // partials per row = NTILES*4
#define L2E     1.4426950408889634f
#define LN2     0.6931471805599453f

// ---------------- SMEM ----------------
#define A_BYTES (BM * 128)              // 32768
#define B_BYTES (BN * 128)              // 32768
#define BUF_B   (A_BYTES + B_BYTES)     // 65536
#define SMEM_DATA 1024
#define SMEM_TOTAL (SMEM_DATA + 3 * BUF_B)   // 197632 -> 1 CTA/SM

// ---------------- device scratch ----------------
__device__ __half g_Wh[2][(size_t)V_DIM * H_DIM];
__device__ __half g_xh[2][(size_t)NROWS * H_DIM];   // pre-scaled by log2(e)
__device__ float2   g_part[(size_t)2 * NROWS * 512];
__device__ float    g_logp[2 * NROWS];
__device__ float    g_maskf[2 * NROWS];
__device__ int      g_y64;
__device__ unsigned g_ticket;

// ---------------- helpers ----------------
__device__ __forceinline__ uint32_t smem_u32(const void* p) {
    uint32_t a;
    asm("{ .reg .u64 t; cvta.to.shared.u64 t, %1; cvt.u32.u64 %0, t; }"
        : "=r"(a) : "l"(p));
    return a;
}

#define SW128(o) ((o) ^ (((o) >> 3) & 0x70))

__device__ __forceinline__ void cp_async16(uint32_t saddr, const void* gaddr) {
    asm volatile("cp.async.cg.shared.global [%0], [%1], 16;"
                 :: "r"(saddr), "l"(gaddr) : "memory");
}

__device__ __forceinline__ void cp_async_mbar_arrive(uint32_t mbar) {
    asm volatile("cp.async.mbarrier.arrive.noinc.shared.b64 [%0];"
                 :: "r"(mbar) : "memory");
}

#define MBARRIER_INIT(addr, cnt) \
    asm volatile("mbarrier.init.shared.b64 [%0], %1;" \
        :: "r"((uint32_t)(addr)), "r"((uint32_t)(cnt)) : "memory")

#define MBARRIER_ARRIVE(addr) \
    asm volatile("mbarrier.arrive.shared.b64 _, [%0];" \
        :: "r"((uint32_t)(addr)) : "memory")

#define MBARRIER_WAIT_PARITY(addr, par) do {                                   \
    uint32_t _mb = (uint32_t)(addr); uint32_t _pp = (uint32_t)(par);           \
    uint32_t _done;                                                            \
    asm volatile("{\n\t.reg .pred p;\n\t"                                      \
        "mbarrier.try_wait.parity.acquire.cta.shared::cta.b64 p, [%1], %2;\n\t"\
        "selp.b32 %0, 1, 0, p;\n\t}"                                           \
        : "=r"(_done) : "r"(_mb), "r"(_pp) : "memory");                        \
    if (!_done) {                                                              \
        asm volatile("{\n\t.reg .pred P1;\n\t"                                 \
            "WAIT_LOOP_%=:\n\t"                                                \
            "mbarrier.try_wait.parity.acquire.cta.shared::cta.b64 P1, [%0], %1, 0x989680;\n\t" \
            "@P1 bra.uni WAIT_DONE_%=;\n\t"                                    \
            "bra.uni WAIT_LOOP_%=;\n\t"                                        \
            "WAIT_DONE_%=:\n\t}"                                               \
            :: "r"(_mb), "r"(_pp) : "memory");                                 \
    }                                                                          \
} while (0)

__device__ __forceinline__ void ldsm_x4(uint32_t (&r)[4], uint32_t addr) {
    asm volatile("ldmatrix.sync.aligned.m8n8.x4.shared.b16 {%0,%1,%2,%3}, [%4];"
        : "=r"(r[0]), "=r"(r[1]), "=r"(r[2]), "=r"(r[3]) : "r"(addr));
}

// fp16 MMA with f16 accumulators: D(16x8) += A(16x16) * B(16x8)
__device__ __forceinline__ void mma16816h(uint32_t (&d)[2], const uint32_t (&a)[4],
                                          uint32_t b0, uint32_t b1) {
    asm volatile(
        "mma.sync.aligned.m16n8k16.row.col.f16.f16.f16.f16 "
        "{%0,%1}, {%2,%3,%4,%5}, {%6,%7}, {%0,%1};"
        : "+r"(d[0]), "+r"(d[1])
        : "r"(a[0]), "r"(a[1]), "r"(a[2]), "r"(a[3]), "r"(b0), "r"(b1));
}

// ---------------- merged fp32 -> fp16 conversion (8 elems/thread) ------
#define WN8 (V_DIM * H_DIM / 8)     // 8,192,000
#define XN8 (NROWS * H_DIM / 8)     // 524,288

__global__ void cvt_all_kernel(const float* __restrict__ x,
                               const float* __restrict__ rx,
                               const float* __restrict__ W,
                               const float* __restrict__ rW) {
    int i = blockIdx.x * blockDim.x + threadIdx.x;
    const float* src;
    __half* dst;
    float scale;
    int off;
    if (i < WN8)                { src = W;  dst = g_Wh[0]; scale = 1.0f; off = i; }
    else if (i < 2 * WN8)       { src = rW; dst = g_Wh[1]; scale = 1.0f; off = i - WN8; }
    else if (i < 2 * WN8 + XN8) { src = x;  dst = g_xh[0]; scale = L2E;  off = i - 2 * WN8; }
    else                        { src = rx; dst = g_xh[1]; scale = L2E;  off = i - 2 * WN8 - XN8; }
    float4 v0 = reinterpret_cast<const float4*>(src)[2 * off];
    float4 v1 = reinterpret_cast<const float4*>(src)[2 * off + 1];
    __half2 h0 = __floats2half2_rn(v0.x * scale, v0.y * scale);
    __half2 h1 = __floats2half2_rn(v0.z * scale, v0.w * scale);
    __half2 h2 = __floats2half2_rn(v1.x * scale, v1.y * scale);
    __half2 h3 = __floats2half2_rn(v1.z * scale, v1.w * scale);
    uint4 o;
    o.x = *reinterpret_cast<unsigned*>(&h0);
    o.y = *reinterpret_cast<unsigned*>(&h1);
    o.z = *reinterpret_cast<unsigned*>(&h2);
    o.w = *reinterpret_cast<unsigned*>(&h3);
    reinterpret_cast<uint4*>(dst)[off] = o;
}

// ---------------- y dtype detect + ticket reset ----------------
__global__ void detect_kernel(const int* __restrict__ y32) {
    if (threadIdx.x == 0) {
        int z = 0;
        for (int i = 0; i < 32; i++)
            if (y32[2 * i + 1] == 0) z++;
        g_y64 = (z >= 28) ? 1 : 0;
        g_ticket = 0;
    }
}

// ---------------- chunk loader: A (256x128B) + B (256x128B) fp16 ------
__device__ __forceinline__ void load_chunk(
    uint32_t dstbase,
    const __half* __restrict__ xr,
    const __half* __restrict__ wp,
    int kc, int tid)
{
    #pragma unroll
    for (int j = 0; j < 8; j++) {                 // A: 2048 x 16B segs
        int idx = j * THREADS + tid;
        int row = idx >> 3, seg = idx & 7;
        uint32_t sa = dstbase + SW128((uint32_t)(row * 128 + seg * 16));
        cp_async16(sa, xr + (size_t)row * H_DIM + kc * BK + seg * 8);
    }
    #pragma unroll
    for (int j = 0; j < 8; j++) {                 // B: 2048 x 16B segs
        int idx = j * THREADS + tid;
        int row = idx >> 3, seg = idx & 7;
        uint32_t sa = dstbase + A_BYTES + SW128((uint32_t)(row * 128 + seg * 16));
        cp_async16(sa, wp + (size_t)row * H_DIM + kc * BK + seg * 8);
    }
}

// decode item -> source pointers + partial slot base
struct ItemPtrs {
    const __half* xr;
    const __half* wp;
    size_t pbase;   // g_part base: (model*NROWS + mgp*256)*512 + nt*4
};
__device__ __forceinline__ ItemPtrs decode_item(unsigned it) {
    unsigned itc = (it < NITEMS) ? it : 0u;
    unsigned nt = itc >> 4;
    unsigned rem = itc & 15u;
    unsigned model = rem >> 3;
    unsigned mgp = rem & 7u;
    ItemPtrs p;
    p.xr = g_xh[model] + (size_t)(mgp * BM) * H_DIM;
    p.wp = g_Wh[model] + (size_t)(nt * BN) * H_DIM;
    p.pbase = ((size_t)(model * NROWS + mgp * BM)) * 512 + nt * 4;
    return p;
}

// ---------------- main fused GEMM (f16 acc, 256x256 block, 3-stage) ----
__global__ void __launch_bounds__(THREADS, 1) dpo_main_kernel() {
    extern __shared__ char smem[];
    const uint32_t sb = smem_u32(smem);
    const int tid = threadIdx.x;
    const int lid = tid & 31;
    const int wid = tid >> 5;
    const int wm  = wid >> 2;       // 0..1 (M position, 128 rows each)
    const int wn  = wid & 3;        // 0..3 (N position, 64 cols each)

    const uint32_t mb_full0  = sb;          // full[b] at sb + b*8
    const uint32_t mb_empty0 = sb + 24;     // empty[b] at sb + 24 + b*8
    unsigned* sm_next = (unsigned*)(smem + 48);

    if (tid == 0) {
        #pragma unroll
        for (int b = 0; b < 3; b++) {
            MBARRIER_INIT(mb_full0  + b * 8, THREADS);
            MBARRIER_INIT(mb_empty0 + b * 8, THREADS);
        }
    }
    __syncthreads();

    // fetch two tickets
    unsigned it0, it1;
    if (tid == 0) *sm_next = atomicAdd(&g_ticket, 1u);
    __syncthreads();
    it0 = *sm_next;
    __syncthreads();
    if (tid == 0) *sm_next = atomicAdd(&g_ticket, 1u);
    __syncthreads();
    it1 = *sm_next;
    __syncthreads();

    if (it0 >= NITEMS) return;

    ItemPtrs cur = decode_item(it0);
    ItemPtrs nxt = decode_item(it1);

    // swizzled base offsets (relative to buffer base; 128B rows, SW128)
    const int a_rowbase = wm * 128 + (lid & 15);
    const uint32_t a_kh = (uint32_t)((lid >> 4) * 16);
    const int b_row0 = wn * 64 + (lid & 7) + ((lid >> 4) << 3);
    const uint32_t b_kh = (uint32_t)(((lid >> 3) & 1) * 16);

    uint32_t a_off[2][4], b_off[4];
    #pragma unroll
    for (int h = 0; h < 2; h++)
        #pragma unroll
        for (int i = 0; i < 4; i++)
            a_off[h][i] = SW128((uint32_t)((a_rowbase + h * 64 + i * 16) * 128) + a_kh);
    #pragma unroll
    for (int j = 0; j < 4; j++)
        b_off[j] = SW128((uint32_t)((b_row0 + j * 16) * 128) + b_kh) + A_BYTES;

    uint32_t acc[2][4][8][2];   // [mgh][i][j][reg] f16x2, warp tile 128x64
    #pragma unroll
    for (int h = 0; h < 2; h++)
        #pragma unroll
        for (int i = 0; i < 4; i++)
            #pragma unroll
            for (int j = 0; j < 8; j++)
                { acc[h][i][j][0] = 0u; acc[h][i][j][1] = 0u; }

    // prologue: chunks 0,1 into buffers 0,1
    load_chunk(sb + SMEM_DATA + 0 * BUF_B, cur.xr, cur.wp, 0, tid);
    cp_async_mbar_arrive(mb_full0 + 0 * 8);
    load_chunk(sb + SMEM_DATA + 1 * BUF_B, cur.xr, cur.wp, 1, tid);
    cp_async_mbar_arrive(mb_full0 + 1 * 8);

    int cc = 0;   // flat chunk counter across items
    #pragma unroll 1
    while (it0 < NITEMS) {
        #pragma unroll 1
        for (int j = 0; j < KCH; j++, cc++) {
            const int b = cc % 3;

            // producer FIRST (3-stage, distance 2): chunk cc+2 -> buffer (cc+2)%3
            const int j2c = j + 2;
            const bool nxtgrp = (j2c >= KCH);
            if (!nxtgrp || it1 < NITEMS) {
                const ItemPtrs& src = nxtgrp ? nxt : cur;
                const int b2 = (cc + 2) % 3;
                if (cc >= 1)
                    MBARRIER_WAIT_PARITY(mb_empty0 + b2 * 8, ((cc - 1) / 3) & 1);
                load_chunk(sb + SMEM_DATA + b2 * BUF_B, src.xr, src.wp,
                           j2c & (KCH - 1), tid);
                cp_async_mbar_arrive(mb_full0 + b2 * 8);
            }

            // consumer: chunk cc
            MBARRIER_WAIT_PARITY(mb_full0 + b * 8, (cc / 3) & 1);

            const uint32_t bufbase = sb + SMEM_DATA + b * BUF_B;
            #pragma unroll
            for (int ks = 0; ks < 4; ks++) {
                const uint32_t kx = (uint32_t)(ks << 5);
                uint32_t b_frag[4][4];
                #pragma unroll
                for (int j2 = 0; j2 < 4; j2++)
                    ldsm_x4(b_frag[j2], (bufbase + b_off[j2]) ^ kx);
                #pragma unroll
                for (int h = 0; h < 2; h++) {
                    uint32_t a_frag[4][4];
                    #pragma unroll
                    for (int i = 0; i < 4; i++)
                        ldsm_x4(a_frag[i], (bufbase + a_off[h][i]) ^ kx);
                    #pragma unroll
                    for (int j2 = 0; j2 < 4; j2++)
                        #pragma unroll
                        for (int i = 0; i < 4; i++) {
                            mma16816h(acc[h][i][j2 * 2],     a_frag[i],
                                      b_frag[j2][0], b_frag[j2][1]);
                            mma16816h(acc[h][i][j2 * 2 + 1], a_frag[i],
                                      b_frag[j2][2], b_frag[j2][3]);
                        }
                }
            }
            MBARRIER_ARRIVE(mb_empty0 + b * 8);
        }

        // epilogue: per-tile max / sum-exp2 over this warp's 64 cols x 128 rows
        #pragma unroll
        for (int h = 0; h < 2; h++) {
            #pragma unroll
            for (int i = 0; i < 4; i++) {
                #pragma unroll
                for (int rh = 0; rh < 2; rh++) {
                    __half2 m2 = __floats2half2_rn(-60000.f, -60000.f);
                    #pragma unroll
                    for (int j = 0; j < 8; j++) {
                        __half2 v = *reinterpret_cast<__half2*>(&acc[h][i][j][rh]);
                        m2 = __hmax2(m2, v);
                    }
                    float2 mf = __half22float2(m2);
                    float rmax = fmaxf(mf.x, mf.y);
                    rmax = fmaxf(rmax, __shfl_xor_sync(0xffffffffu, rmax, 1));
                    rmax = fmaxf(rmax, __shfl_xor_sync(0xffffffffu, rmax, 2));
                    __half2 rm2 = __float2half2_rn(rmax);
                    __half2 s2 = __float2half2_rn(0.f);
                    #pragma unroll
                    for (int j = 0; j < 8; j++) {
                        __half2 v = *reinterpret_cast<__half2*>(&acc[h][i][j][rh]);
                        s2 = __hadd2(s2, h2exp2(__hsub2(v, rm2)));
                    }
                    float2 sf = __half22float2(s2);
                    float st = sf.x + sf.y;
                    st += __shfl_xor_sync(0xffffffffu, st, 1);
                    st += __shfl_xor_sync(0xffffffffu, st, 2);
                    if ((lid & 3) == 0) {
                        int row = wm * 128 + h * 64 + i * 16 + rh * 8 + (lid >> 2);
                        g_part[cur.pbase + (size_t)row * 512 + wn] =
                            make_float2(rmax, st);
                    }
                }
            }
        }
        #pragma unroll
        for (int h = 0; h < 2; h++)
            #pragma unroll
            for (int i = 0; i < 4; i++)
                #pragma unroll
                for (int j = 0; j < 8; j++)
                    { acc[h][i][j][0] = 0u; acc[h][i][j][1] = 0u; }

        // rotate items; fetch new lookahead ticket
        it0 = it1;
        cur = nxt;
        __syncthreads();
        if (tid == 0)
            *sm_next = (it0 < NITEMS) ? atomicAdd(&g_ticket, 1u) : NITEMS;
        __syncthreads();
        it1 = *sm_next;
        nxt = decode_item(it1);
    }
}

// ---------------- combine 500 partials/row + exact fp32 token dot -----
__global__ void reduce_kernel(const void* __restrict__ yp,
                              const float* __restrict__ x,
                              const float* __restrict__ rx,
                              const float* __restrict__ W,
                              const float* __restrict__ rW) {
    int wid = threadIdx.x >> 5, lid = threadIdx.x & 31;
    int row_all = blockIdx.x * 8 + wid;        // 512 blocks -> 4096 rows
    if (row_all >= 2 * NROWS) return;
    int model = row_all >> 11;
    int r     = row_all & (NROWS - 1);

    long long yv = g_y64 ? ((const long long*)yp)[r]
                         : (long long)((const int*)yp)[r];
    bool mask = (yv != -100);
    int safe = mask ? (int)yv : 0;

    // exact token logit from ORIGINAL fp32 inputs (natural units)
    const float4* xr = (const float4*)((model ? rx : x) + (size_t)r * H_DIM);
    const float4* wr = (const float4*)((model ? rW : W) + (size_t)safe * H_DIM);
    float acc = 0.f;
    #pragma unroll 4
    for (int t = 0; t < 16; t++) {
        int i = t * 32 + lid;
        float4 a = xr[i];
        float4 b = wr[i];
        acc = fmaf(a.x, b.x, acc);
        acc = fmaf(a.y, b.y, acc);
        acc = fmaf(a.z, b.z, acc);
        acc = fmaf(a.w, b.w, acc);
    }
    #pragma unroll
    for (int off = 16; off; off >>= 1)
        acc += __shfl_xor_sync(0xffffffffu, acc, off);

    // combine PARTS = 500 (m, s) partials for this row
    const float2* pp = &g_part[((size_t)(model * NROWS + r)) * 512];
    float M = -3.0e38f, S = 0.f;
    for (int t = 0; t < 16; t++) {
        int idx = t * 32 + lid;
        if (idx < PARTS) {
            float2 v = pp[idx];
            float mnew = fmaxf(M, v.x);
            S = S * exp2f(M - mnew) + v.y * exp2f(v.x - mnew);
            M = mnew;
        }
    }
    #pragma unroll
    for (int off = 16; off; off >>= 1) {
        float Mo = __shfl_xor_sync(0xffffffffu, M, off);
        float So = __shfl_xor_sync(0xffffffffu, S, off);
        float mnew = fmaxf(M, Mo);
        S = S * exp2f(M - mnew) + So * exp2f(Mo - mnew);
        M = mnew;
    }
    float lse_nat = LN2 * (M + log2f(S));
    if (lid == 0) {
        g_logp[row_all]  = mask ? (acc - lse_nat) : 0.f;
        g_maskf[row_all] = mask ? 1.f : 0.f;
    }
}

// ---------------- final loss ----------------
__global__ void final_kernel(float* __restrict__ out) {
    __shared__ float avg[8];
    int wid = threadIdx.x >> 5, lid = threadIdx.x & 31;
    float sl = 0.f, sm = 0.f;
    for (int i = lid; i < 512; i += 32) {
        sl += g_logp[wid * 512 + i];
        sm += g_maskf[wid * 512 + i];
    }
    #pragma unroll
    for (int off = 16; off; off >>= 1) {
        sl += __shfl_xor_sync(0xffffffffu, sl, off);
        sm += __shfl_xor_sync(0xffffffffu, sm, off);
    }
    if (lid == 0) avg[wid] = (sm > 0.f) ? (sl / sm) : 0.f;
    __syncthreads();
    if (threadIdx.x == 0) {
        const float BETA = 0.1f;
        float loss = 0.f;
        for (int b = 0; b < 4; b++) {
            float lr = avg[b] - avg[4 + b];
            float z = (b < 2) ? (BETA * lr) : (-BETA * lr);
            float sig = 1.f / (1.f + expf(-z));
            loss += 1.f - sig;
        }
        out[0] = loss / 2.f;
    }
}

// ---------------- launcher ----------------
extern "C" void kernel_launch(void* const* d_in, const int* in_sizes, int n_in,
                              void* d_out, int out_size) {
    const float* x  = (const float*)d_in[0];
    const float* rx = (const float*)d_in[1];
    const void*  y  = d_in[2];
    const float* W  = (const float*)d_in[3];
    const float* rW = (const float*)d_in[4];
    float* out = (float*)d_out;

    cudaFuncSetAttribute(dpo_main_kernel,
                         cudaFuncAttributeMaxDynamicSharedMemorySize, SMEM_TOTAL);

    const int cvt_blocks = (2 * WN8 + 2 * XN8) / 256;   // 68096 exact
    cvt_all_kernel<<<cvt_blocks, 256>>>(x, rx, W, rW);
    detect_kernel<<<1, 32>>>((const int*)y);
    dpo_main_kernel<<<GRID, THREADS, SMEM_TOTAL>>>();
    reduce_kernel<<<512, 256>>>(y, x, rx, W, rW);
    final_kernel<<<1, 256>>>(out);
}